// round 1
// baseline (speedup 1.0000x reference)
#include <cuda_runtime.h>

#define N_NODES 50000
#define N_EDGES 500000
#define NUMK 4
#define FDIM 64
#define DDIM 32
#define NBE 64
#define NBND 63
#define GP 68   // shared-memory row pitch (floats) for GEMM tiles

// Scratch (device globals: no allocation allowed)
__device__ __align__(128) float g_y[(size_t)N_NODES * 128];  // per-node accumulated cat (25.6 MB)
__device__ float g_s[N_NODES];                               // per-node accumulated scale
__device__ float g_d0[N_NODES];                              // in_deg -> rsqrt
__device__ float g_d2[N_NODES];                              // out_deg -> rsqrt
__device__ __align__(128) float g_T[NBE * FDIM];             // bucket -> (embed @ G_w.T) table

__device__ __forceinline__ void red_add4(float* p, float x, float y, float z, float w) {
    asm volatile("red.global.add.v4.f32 [%0], {%1,%2,%3,%4};"
                 :: "l"(p), "f"(x), "f"(y), "f"(z), "f"(w) : "memory");
}

__global__ void k_zero() {
    int i = blockIdx.x * blockDim.x + threadIdx.x;
    int stride = gridDim.x * blockDim.x;
    float4 z = make_float4(0.f, 0.f, 0.f, 0.f);
    float4* y4 = reinterpret_cast<float4*>(g_y);
    for (int j = i; j < N_NODES * 32; j += stride) y4[j] = z;
    for (int j = i; j < N_NODES; j += stride) { g_s[j] = 0.f; g_d0[j] = 0.f; g_d2[j] = 0.f; }
}

// T[b][f] = sum_d embed[b][d] * G_w[f][d]
__global__ void k_table(const float* __restrict__ emb, const float* __restrict__ gw) {
    int b = blockIdx.x, f = threadIdx.x;
    float acc = 0.f;
#pragma unroll
    for (int d = 0; d < DDIM; d++) acc += emb[b * DDIM + d] * gw[f * DDIM + d];
    g_T[b * FDIM + f] = acc;
}

__global__ void k_deg(const int* __restrict__ src, const int* __restrict__ dst) {
    int e = blockIdx.x * blockDim.x + threadIdx.x;
    if (e < N_EDGES) {
        atomicAdd(&g_d0[dst[e]], 1.f);
        atomicAdd(&g_d2[src[e]], 1.f);
    }
}

__global__ void k_norm() {
    int i = blockIdx.x * blockDim.x + threadIdx.x;
    if (i < N_NODES) {
        g_d0[i] = rsqrtf(fmaxf(g_d0[i], 1.f));
        g_d2[i] = rsqrtf(fmaxf(g_d2[i], 1.f));
    }
}

// One warp per edge. Accumulate y[dst] += sc * cat, s[dst] += sc.
__global__ __launch_bounds__(256) void k_edge(
    const float* __restrict__ feat, const float* __restrict__ loc,
    const float* __restrict__ bnd,
    const int* __restrict__ src, const int* __restrict__ dst,
    const int* __restrict__ inter)
{
    __shared__ float sb[64];
    int t = threadIdx.x;
    if (t < NBND) sb[t] = bnd[t];
    __syncthreads();

    int lane = t & 31;
    int e = blockIdx.x * 8 + (t >> 5);
    if (e >= N_EDGES) return;

    int si = __ldg(&src[e]);
    int di = __ldg(&dst[e]);

    int other = 0, pos = 0;
    if (lane < 5) {
        other = (lane == 0) ? di : __ldg(&inter[e * NUMK + lane - 1]);
        float ax = __ldg(&loc[si * 3]),    ay = __ldg(&loc[si * 3 + 1]),    az = __ldg(&loc[si * 3 + 2]);
        float bx = __ldg(&loc[other * 3]), by = __ldg(&loc[other * 3 + 1]), bz = __ldg(&loc[other * 3 + 2]);
        float dx = ax - bx, dy = ay - by, dz = az - bz;
        float dv = sqrtf(dx * dx + dy * dy + dz * dz);
        // searchsorted(boundaries, dv, side='left') == count(boundaries < dv)
#pragma unroll
        for (int step = 32; step >= 1; step >>= 1)
            if (pos + step <= NBND && sb[pos + step - 1] < dv) pos += step;
    }
    unsigned m = 0xffffffffu;
    int b1  = __shfl_sync(m, pos, 0);
    int bk0 = __shfl_sync(m, pos, 1), bk1 = __shfl_sync(m, pos, 2);
    int bk2 = __shfl_sync(m, pos, 3), bk3 = __shfl_sync(m, pos, 4);
    int i0  = __shfl_sync(m, other, 1), i1 = __shfl_sync(m, other, 2);
    int i2  = __shfl_sync(m, other, 3), i3 = __shfl_sync(m, other, 4);

    float sc = __ldg(&g_d0[di]) * __ldg(&g_d2[si]);
    float* yrow = g_y + (size_t)di * 128;

    if (lane < 16) {
        int j = lane * 4;
        float4 h  = *reinterpret_cast<const float4*>(feat + (size_t)si * FDIM + j);
        float4 tt = *reinterpret_cast<const float4*>(g_T + b1 * FDIM + j);
        red_add4(yrow + j, sc * h.x * tt.x, sc * h.y * tt.y, sc * h.z * tt.z, sc * h.w * tt.w);
        if (lane == 0) atomicAdd(&g_s[di], sc);
    } else {
        int j = (lane - 16) * 4;
        float ax = 0.f, ay = 0.f, az = 0.f, aw = 0.f;
        int ids[4] = {i0, i1, i2, i3};
        int bks[4] = {bk0, bk1, bk2, bk3};
#pragma unroll
        for (int k = 0; k < NUMK; k++) {
            float4 h  = *reinterpret_cast<const float4*>(feat + (size_t)ids[k] * FDIM + j);
            float4 tt = *reinterpret_cast<const float4*>(g_T + bks[k] * FDIM + j);
            ax += h.x * tt.x; ay += h.y * tt.y; az += h.z * tt.z; aw += h.w * tt.w;
        }
        float f4 = sc * 0.25f;
        red_add4(yrow + 64 + j, f4 * ax, f4 * ay, f4 * az, f4 * aw);
    }
}

// out[v][f] = sum_j y[v][j] * W[f][j] + s[v] * b[f]
// Block: 64 nodes x 64 f, 256 threads, each thread a 4(v) x 4(f) register tile.
__global__ __launch_bounds__(256) void k_gemm(
    const float* __restrict__ W, const float* __restrict__ bvec,
    float* __restrict__ out)
{
    extern __shared__ float smem[];
    float* sW = smem;             // [128][GP], j-major, indexed by f
    float* sY = smem + 128 * GP;  // [128][GP], j-major, indexed by v_local
    int t = threadIdx.x;
    int vbase = blockIdx.x * 64;

    for (int idx = t; idx < FDIM * 128; idx += 256) {
        int f = idx >> 7, j = idx & 127;
        sW[j * GP + f] = W[idx];
    }
    for (int idx = t; idx < 64 * 128; idx += 256) {
        int v = idx >> 7, j = idx & 127;
        int gv = vbase + v;
        sY[j * GP + v] = (gv < N_NODES) ? g_y[(size_t)gv * 128 + j] : 0.f;
    }
    __syncthreads();

    int f0 = (t & 15) * 4;
    int v0 = (t >> 4) * 4;
    float acc[4][4];
#pragma unroll
    for (int a = 0; a < 4; a++)
#pragma unroll
        for (int b = 0; b < 4; b++) acc[a][b] = 0.f;

#pragma unroll 4
    for (int j = 0; j < 128; j++) {
        float4 wv = *reinterpret_cast<float4*>(&sW[j * GP + f0]);
        float4 yv = *reinterpret_cast<float4*>(&sY[j * GP + v0]);
        float w[4] = {wv.x, wv.y, wv.z, wv.w};
        float y[4] = {yv.x, yv.y, yv.z, yv.w};
#pragma unroll
        for (int a = 0; a < 4; a++)
#pragma unroll
            for (int b = 0; b < 4; b++) acc[a][b] += y[a] * w[b];
    }

    float4 bb = *reinterpret_cast<const float4*>(bvec + f0);
#pragma unroll
    for (int a = 0; a < 4; a++) {
        int v = vbase + v0 + a;
        if (v < N_NODES) {
            float sv = g_s[v];
            float4 o;
            o.x = acc[a][0] + sv * bb.x;
            o.y = acc[a][1] + sv * bb.y;
            o.z = acc[a][2] + sv * bb.z;
            o.w = acc[a][3] + sv * bb.w;
            *reinterpret_cast<float4*>(out + (size_t)v * FDIM + f0) = o;
        }
    }
}

extern "C" void kernel_launch(void* const* d_in, const int* in_sizes, int n_in,
                              void* d_out, int out_size) {
    const float* feat = (const float*)d_in[0];
    const float* loc  = (const float*)d_in[1];
    const float* bnd  = (const float*)d_in[2];
    const float* emb  = (const float*)d_in[3];
    const float* gw   = (const float*)d_in[4];
    const float* aggw = (const float*)d_in[5];
    const float* aggb = (const float*)d_in[6];
    const int* src   = (const int*)d_in[7];
    const int* dst   = (const int*)d_in[8];
    const int* inter = (const int*)d_in[9];
    float* out = (float*)d_out;

    k_zero<<<1024, 256>>>();
    k_table<<<NBE, FDIM>>>(emb, gw);
    k_deg<<<(N_EDGES + 255) / 256, 256>>>(src, dst);
    k_norm<<<(N_NODES + 255) / 256, 256>>>();
    k_edge<<<(N_EDGES + 7) / 8, 256>>>(feat, loc, bnd, src, dst, inter);

    size_t smem = 2 * 128 * GP * sizeof(float);  // 69632 B
    cudaFuncSetAttribute(k_gemm, cudaFuncAttributeMaxDynamicSharedMemorySize, (int)smem);
    k_gemm<<<(N_NODES + 63) / 64, 256, smem>>>(aggw, aggb, out);
}